// round 13
// baseline (speedup 1.0000x reference)
#include <cuda_runtime.h>

#define NBLK 32
#define NTHR 512

// ---------------- f32x2 helpers ----------------
typedef unsigned long long ull;

__device__ __forceinline__ float2 unpack2(ull v) {
    float2 f; asm("mov.b64 {%0, %1}, %2;" : "=f"(f.x), "=f"(f.y) : "l"(v)); return f;
}
__device__ __forceinline__ ull ffma2(ull a, ull b, ull c) {
    ull d; asm("fma.rn.f32x2 %0, %1, %2, %3;" : "=l"(d) : "l"(a), "l"(b), "l"(c)); return d;
}

// dynamic smem layout (floats)
#define OFF_SIG  0          // 1504
#define OFF_CTX  1504       // 8 x 1504 = 12032
#define OFF_H1   13536      // 32 x 376 = 12032  (moments coef/vv + later w3 staged here too)
#define OFF_H2   25568      // 64 x 96 = 6144
#define OFF_W1   31712      // 2048
#define OFF_W2   33760      // 16384
#define SMEM_FLOATS 50144   // 200576 bytes

// ================= one block = one batch, zero inter-block sync =================
__global__ void __launch_bounds__(NTHR, 1) fused_kernel(
        const float* __restrict__ sig,
        const float* __restrict__ wq, const float* __restrict__ bq,
        const float* __restrict__ wk, const float* __restrict__ bk,
        const float* __restrict__ wv, const float* __restrict__ bv,
        const float* __restrict__ w1, const float* __restrict__ b1,
        const float* __restrict__ w2, const float* __restrict__ b2,
        const float* __restrict__ w3, const float* __restrict__ b3,
        const float* __restrict__ wl, const float* __restrict__ bl,
        float* __restrict__ out) {
    extern __shared__ float smbuf[];
    __shared__ float cw[96];    // [0:24)wq [24:48)wk [48:72)wv [72:80)bq [80:88)bk [88:96)bv
    __shared__ float Pm[16];
    __shared__ float Es[184];
    __shared__ float flat[176];

    const int tid  = threadIdx.x;
    const int warp = tid >> 5;
    const int lane = tid & 31;
    const int b    = blockIdx.x;

    const float QS = 0.02581988897471611f;  // 1/sqrt(1500)
    const float C6 = 0.16666666666666666f;

    float* sigS = smbuf + OFF_SIG;
    float* ctx  = smbuf + OFF_CTX;   // [8][1504]
    float* h1   = smbuf + OFF_H1;    // [32][376]
    float* h2   = smbuf + OFF_H2;    // [64][96]
    float* w1s  = smbuf + OFF_W1;    // 2048
    float* w2s  = smbuf + OFF_W2;    // 16384

    // ---- load constants / signal / weights ----
    if (tid < 24)      cw[tid] = wq[tid];
    else if (tid < 48) cw[tid] = wk[tid - 24];
    else if (tid < 72) cw[tid] = wv[tid - 48];
    else if (tid < 80) cw[tid] = bq[tid - 72];
    else if (tid < 88) cw[tid] = bk[tid - 80];
    else if (tid < 96) cw[tid] = bv[tid - 88];
    else if (tid < 112) {
        // Pm[j][i] = QS * sum_c (j<3 ? wq[c*3+j] : bq[c]) * (i<3 ? wk[c*3+i] : bk[c])
        int p = tid - 96, j = p >> 2, i = p & 3;
        float s = 0.f;
#pragma unroll
        for (int c = 0; c < 8; c++) {
            float qv = (j < 3) ? wq[c*3 + j] : bq[c];
            float kv = (i < 3) ? wk[c*3 + i] : bk[c];
            s = fmaf(qv, kv, s);
        }
        Pm[p] = s * QS;
    }
    {
        const float* sigb = sig + b * 1500;
        for (int i = tid; i < 1500; i += NTHR) sigS[i] = sigb[i];
        if (tid < 4) sigS[1500 + tid] = 0.f;
        for (int i = tid; i < 2048; i += NTHR) w1s[i] = w1[i];
        const float4* w4 = (const float4*)w2;
        float4* ws4 = (float4*)w2s;
        for (int i = tid; i < 4096; i += NTHR) ws4[i] = w4[i];
    }

    // ---- Phase 1: moments (4 m-tiles of 375, coef/vv in h1 region) ----
    {
        float* coef = h1;              // [20][376]
        float* vv   = h1 + 20 * 376;   // [9][376], row 8 = ones
        // zero pad column 375 once
        if (tid < 20) coef[tid * 376 + 375] = 0.f;
        else if (tid < 29) vv[(tid - 20) * 376 + 375] = 0.f;

        ull psum2[12];
#pragma unroll
        for (int pi = 0; pi < 12; pi++) psum2[pi] = 0ull;

        const ull* coef2 = (const ull*)coef;   // stride 188
        const ull* vv2   = (const ull*)vv;

        for (int T = 0; T < 4; T++) {
            __syncthreads();   // prior dots done / initial loads visible
            for (int j = tid; j < 375; j += NTHR) {
                int m = T * 375 + j;
                float xm1 = (m > 0)    ? sigS[m - 1] : 0.f;
                float x0  = sigS[m];
                float xp1 = (m < 1499) ? sigS[m + 1] : 0.f;
                float a0 = fmaf(Pm[0],  xm1, fmaf(Pm[1],  x0, fmaf(Pm[2],  xp1, Pm[3])));
                float a1 = fmaf(Pm[4],  xm1, fmaf(Pm[5],  x0, fmaf(Pm[6],  xp1, Pm[7])));
                float a2 = fmaf(Pm[8],  xm1, fmaf(Pm[9],  x0, fmaf(Pm[10], xp1, Pm[11])));
                float a3 = fmaf(Pm[12], xm1, fmaf(Pm[13], x0, fmaf(Pm[14], xp1, Pm[15])));

                float p1 = fmaf(a3, fmaf(0.5f, a3, 1.f), 1.f);     // 1 + a3 + a3^2/2
                float p0 = fmaf(a3 * a3 * a3, C6, p1);             // + a3^3/6
                float p2 = fmaf(0.5f, a3, 0.5f);
                float q2 = a3 + 1.f;

                float a00 = a0*a0, a01 = a0*a1, a02 = a0*a2;
                float a11 = a1*a1, a12 = a1*a2, a22 = a2*a2;

                coef[ 0*376 + j] = p0;
                coef[ 1*376 + j] = p1 * a0;
                coef[ 2*376 + j] = p1 * a1;
                coef[ 3*376 + j] = p1 * a2;
                coef[ 4*376 + j] = p2 * a00;
                coef[ 5*376 + j] = q2 * a01;
                coef[ 6*376 + j] = q2 * a02;
                coef[ 7*376 + j] = p2 * a11;
                coef[ 8*376 + j] = q2 * a12;
                coef[ 9*376 + j] = p2 * a22;
                coef[10*376 + j] = C6  * a00 * a0;
                coef[11*376 + j] = 0.5f * a00 * a1;
                coef[12*376 + j] = 0.5f * a00 * a2;
                coef[13*376 + j] = 0.5f * a0  * a11;
                coef[14*376 + j] =        a01 * a2;
                coef[15*376 + j] = 0.5f * a0  * a22;
                coef[16*376 + j] = C6  * a11 * a1;
                coef[17*376 + j] = 0.5f * a11 * a2;
                coef[18*376 + j] = 0.5f * a1  * a22;
                coef[19*376 + j] = C6  * a22 * a2;
#pragma unroll
                for (int c = 0; c < 8; c++) {
                    vv[c*376 + j] = fmaf(cw[48 + c*3], xm1,
                                     fmaf(cw[49 + c*3], x0,
                                     fmaf(cw[50 + c*3], xp1, cw[88 + c])));
                }
                vv[8*376 + j] = 1.f;
            }
            __syncthreads();

            // packed dots: warp handles pairs warp, warp+16, ... (lane partials in regs)
#pragma unroll
            for (int pi = 0; pi < 12; pi++) {
                int pair = warp + pi * 16;
                if (pair < 180) {
                    int t = pair / 9, c = pair % 9;
                    const ull* cp = coef2 + t * 188;
                    const ull* vp = vv2   + c * 188;
                    ull s2 = psum2[pi];
                    for (int j = lane; j < 188; j += 32) s2 = ffma2(cp[j], vp[j], s2);
                    psum2[pi] = s2;
                }
            }
        }
        // reduce and publish Es
#pragma unroll
        for (int pi = 0; pi < 12; pi++) {
            int pair = warp + pi * 16;
            if (pair < 180) {
                float2 f = unpack2(psum2[pi]);
                float s = f.x + f.y;
#pragma unroll
                for (int off = 16; off; off >>= 1) s += __shfl_xor_sync(0xffffffffu, s, off);
                if (lane == 0) Es[pair] = s;
            }
        }
        __syncthreads();
    }

    // ---- Phase 2: evaluate ctx[8][1500] ----
    for (int l = tid; l < 1500; l += NTHR) {
        float y0 = (l > 0)    ? sigS[l - 1] : 0.f;
        float y1 = sigS[l];
        float y2 = (l < 1499) ? sigS[l + 1] : 0.f;
        float u[20];
        u[0] = 1.f;  u[1] = y0;  u[2] = y1;  u[3] = y2;
        u[4] = y0*y0; u[5] = y0*y1; u[6] = y0*y2; u[7] = y1*y1; u[8] = y1*y2; u[9] = y2*y2;
        u[10] = u[4]*y0; u[11] = u[4]*y1; u[12] = u[4]*y2; u[13] = y0*u[7]; u[14] = u[5]*y2;
        u[15] = y0*u[9]; u[16] = u[7]*y1; u[17] = u[7]*y2; u[18] = y1*u[9]; u[19] = u[9]*y2;

        float cx[8] = {0,0,0,0,0,0,0,0};
        float den = 0.f;
#pragma unroll
        for (int t = 0; t < 20; t++) {
            float ut = u[t];
            den = fmaf(ut, Es[t*9 + 8], den);
#pragma unroll
            for (int c = 0; c < 8; c++) cx[c] = fmaf(ut, Es[t*9 + c], cx[c]);
        }
        float inv = 1.f / den;
#pragma unroll
        for (int c = 0; c < 8; c++) ctx[c * 1504 + l] = cx[c] * inv;
    }
    __syncthreads();   // ctx ready (also: moments' coef region now reusable as h1)

    // ---- Phase 3: conv1 (8->32 ch, k8 s4) -> h1 smem ----
    {
        const ull* xsu = (const ull*)ctx;   // row stride 752
        const ull* wsu = (const ull*)w1s;   // [co][ci][kpair]
        int cob  = (warp & 7) * 4;
        int half = warp >> 3;
        for (int tile = half * 6; tile < half * 6 + 6; tile++) {
            int lo = tile * 32 + lane;
            ull acc[4] = {0ull, 0ull, 0ull, 0ull};
#pragma unroll
            for (int ci = 0; ci < 8; ci++) {
                ull x[4];
#pragma unroll
                for (int kp = 0; kp < 4; kp++) x[kp] = xsu[ci * 752 + 2 * lo + kp];
#pragma unroll
                for (int co = 0; co < 4; co++)
#pragma unroll
                    for (int kp = 0; kp < 4; kp++)
                        acc[co] = ffma2(wsu[(cob + co) * 32 + ci * 4 + kp], x[kp], acc[co]);
            }
            if (lo < 374) {
#pragma unroll
                for (int co = 0; co < 4; co++) {
                    float2 f = unpack2(acc[co]);
                    h1[(cob + co) * 376 + lo] = f.x + f.y + b1[cob + co];
                }
            }
        }
    }
    __syncthreads();   // h1 ready

    // ---- Phase 4: conv2 (32->64 ch, k8 s4) -> h2 smem ----
    {
        const ull* xsu = (const ull*)h1;    // row stride 188
        const ull* wsu = (const ull*)w2s;   // [co][ci][kpair]: co*128 + ci*4 + kp
        int cob = warp * 4;
        for (int t = 0; t < 3; t++) {
            int lo = t * 32 + lane;
            ull acc[4] = {0ull, 0ull, 0ull, 0ull};
            ull xa[4], xb[4];
#pragma unroll
            for (int kp = 0; kp < 4; kp++) xa[kp] = xsu[2 * lo + kp];
#pragma unroll
            for (int ci = 0; ci < 32; ci += 2) {
#pragma unroll
                for (int kp = 0; kp < 4; kp++) xb[kp] = xsu[(ci + 1) * 188 + 2 * lo + kp];
#pragma unroll
                for (int j = 0; j < 4; j++)
#pragma unroll
                    for (int kp = 0; kp < 4; kp++)
                        acc[j] = ffma2(wsu[(cob + j) * 128 + ci * 4 + kp], xa[kp], acc[j]);
                if (ci + 2 < 32) {
#pragma unroll
                    for (int kp = 0; kp < 4; kp++) xa[kp] = xsu[(ci + 2) * 188 + 2 * lo + kp];
                }
#pragma unroll
                for (int j = 0; j < 4; j++)
#pragma unroll
                    for (int kp = 0; kp < 4; kp++)
                        acc[j] = ffma2(wsu[(cob + j) * 128 + (ci + 1) * 4 + kp], xb[kp], acc[j]);
            }
            if (lo < 92) {
#pragma unroll
                for (int j = 0; j < 4; j++) {
                    float2 f = unpack2(acc[j]);
                    h2[(cob + j) * 96 + lo] = f.x + f.y + b2[cob + j];
                }
            }
        }
    }
    __syncthreads();   // h2 ready; h1 region free -> stage w3

    // ---- Phase 5: conv3 (64->8) + linear ----
    {
        float* w3s = h1;   // 4096 floats staged into freed h1 region
        for (int i = tid; i < 4096; i += NTHR) w3s[i] = w3[i];
        __syncthreads();

        if (warp < 8 && lane < 22) {
            float acc = b3[warp];
            const float* wp = w3s + warp * 512;
#pragma unroll 8
            for (int ci = 0; ci < 64; ci++) {
                const float4* xp = (const float4*)(h2 + ci * 96 + 4 * lane);
                float4 x0 = xp[0], x1 = xp[1];
                const float* w = wp + ci * 8;
                acc += w[0]*x0.x + w[1]*x0.y + w[2]*x0.z + w[3]*x0.w
                     + w[4]*x1.x + w[5]*x1.y + w[6]*x1.z + w[7]*x1.w;
            }
            flat[warp * 22 + lane] = acc;
        }
        __syncthreads();

        if (warp < 3) {
            float s = 0.f;
            for (int i = lane; i < 176; i += 32) s += wl[warp * 176 + i] * flat[i];
#pragma unroll
            for (int off = 16; off; off >>= 1) s += __shfl_xor_sync(0xffffffffu, s, off);
            if (lane == 0) out[b * 3 + warp] = s + bl[warp];
        }
    }
}

// ---------------- launch ----------------
extern "C" void kernel_launch(void* const* d_in, const int* in_sizes, int n_in,
                              void* d_out, int out_size) {
    const float* signal = (const float*)d_in[0];
    const float* wq = (const float*)d_in[1];
    const float* bq = (const float*)d_in[2];
    const float* wk = (const float*)d_in[3];
    const float* bk = (const float*)d_in[4];
    const float* wv = (const float*)d_in[5];
    const float* bv = (const float*)d_in[6];
    const float* w1 = (const float*)d_in[7];
    const float* b1 = (const float*)d_in[8];
    const float* w2 = (const float*)d_in[9];
    const float* b2 = (const float*)d_in[10];
    const float* w3 = (const float*)d_in[11];
    const float* b3 = (const float*)d_in[12];
    const float* wl = (const float*)d_in[13];
    const float* bl = (const float*)d_in[14];
    float* out = (float*)d_out;

    cudaFuncSetAttribute(fused_kernel, cudaFuncAttributeMaxDynamicSharedMemorySize,
                         SMEM_FLOATS * 4);
    fused_kernel<<<NBLK, NTHR, SMEM_FLOATS * 4>>>(signal, wq, bq, wk, bk, wv, bv,
                                                  w1, b1, w2, b2, w3, b3, wl, bl, out);
}

// round 14
// speedup vs baseline: 1.3243x; 1.3243x over previous
#include <cuda_runtime.h>

#define NBLK 64
#define NTHR 512

// ---------------- scratch (no allocs allowed) ----------------
__device__ float g_h2[32 * 64 * 96];     // [b][co][col], col padded 92->96
__device__ unsigned g_pH[32];            // head ticket per batch (target 2)

// ---------------- f32x2 helpers ----------------
typedef unsigned long long ull;

__device__ __forceinline__ float2 unpack2(ull v) {
    float2 f; asm("mov.b64 {%0, %1}, %2;" : "=f"(f.x), "=f"(f.y) : "l"(v)); return f;
}
__device__ __forceinline__ ull ffma2(ull a, ull b, ull c) {
    ull d; asm("fma.rn.f32x2 %0, %1, %2, %3;" : "=l"(d) : "l"(a), "l"(b), "l"(c)); return d;
}

// dynamic smem layout (floats)
#define OFF_SIG  0          // 1504
#define OFF_CTX  1504       // 8 x 776 = 6208   (window of ctx columns)
#define OFF_H1   7712       // 32 x 192 = 6144  (window of h1 columns)
#define OFF_W1   13856      // 2048
#define OFF_W2   15904      // 16384
#define SMEM_FLOATS 32288   // 129152 bytes
// moment scratch aliases [OFF_CTX, OFF_W1): coef 20x376 @1504, vv 9x376 @9024

// ================= block = (batch, half); one atomic per batch =================
__global__ void __launch_bounds__(NTHR, 1) fused_kernel(
        const float* __restrict__ sig,
        const float* __restrict__ wq, const float* __restrict__ bq,
        const float* __restrict__ wk, const float* __restrict__ bk,
        const float* __restrict__ wv, const float* __restrict__ bv,
        const float* __restrict__ w1, const float* __restrict__ b1,
        const float* __restrict__ w2, const float* __restrict__ b2,
        const float* __restrict__ w3, const float* __restrict__ b3,
        const float* __restrict__ wl, const float* __restrict__ bl,
        float* __restrict__ out) {
    extern __shared__ float smbuf[];
    __shared__ float cw[96];    // [48:72)wv [88:96)bv used; rest staged anyway
    __shared__ float Pm[16];
    __shared__ float Es[184];
    __shared__ float flat[176];
    __shared__ unsigned svH;

    const int tid  = threadIdx.x;
    const int warp = tid >> 5;
    const int lane = tid & 31;
    const int b    = blockIdx.x >> 1;
    const int h    = blockIdx.x & 1;

    const float QS = 0.02581988897471611f;  // 1/sqrt(1500)
    const float C6 = 0.16666666666666666f;

    float* sigS = smbuf + OFF_SIG;
    float* ctx  = smbuf + OFF_CTX;   // [8][776], global col = 724*h + j
    float* h1s  = smbuf + OFF_H1;    // [32][192], global lo = 184*h + ll
    float* w1s  = smbuf + OFF_W1;
    float* w2s  = smbuf + OFF_W2;

    const int cbase = 724 * h;   // ctx window base (h1: 724..1499)
    const int lbase = 184 * h;   // h1 window base  (h1: 184..373)

    // ---- load constants / signal / weights ----
    if (tid < 24)      cw[tid] = wq[tid];
    else if (tid < 48) cw[tid] = wk[tid - 24];
    else if (tid < 72) cw[tid] = wv[tid - 48];
    else if (tid < 80) cw[tid] = bq[tid - 72];
    else if (tid < 88) cw[tid] = bk[tid - 80];
    else if (tid < 96) cw[tid] = bv[tid - 88];
    else if (tid < 112) {
        int p = tid - 96, j = p >> 2, i = p & 3;
        float s = 0.f;
#pragma unroll
        for (int c = 0; c < 8; c++) {
            float qv = (j < 3) ? wq[c*3 + j] : bq[c];
            float kv = (i < 3) ? wk[c*3 + i] : bk[c];
            s = fmaf(qv, kv, s);
        }
        Pm[p] = s * QS;
    }
    {
        const float* sigb = sig + b * 1500;
        for (int i = tid; i < 1500; i += NTHR) sigS[i] = sigb[i];
        if (tid < 4) sigS[1500 + tid] = 0.f;
        for (int i = tid; i < 2048; i += NTHR) w1s[i] = w1[i];
        const float4* w4 = (const float4*)w2;
        float4* ws4 = (float4*)w2s;
        for (int i = tid; i < 4096; i += NTHR) ws4[i] = w4[i];
    }

    // ---- Phase 1: moments over full m (4 tiles of 375), register-tiled dots ----
    {
        float* coef = smbuf + 1504;   // [20][376]
        float* vv   = smbuf + 9024;   // [9][376], row 8 = ones
        if (tid < 20) coef[tid * 376 + 375] = 0.f;
        else if (tid < 29) vv[(tid - 20) * 376 + 375] = 0.f;

        const ull* coef2 = (const ull*)coef;   // stride 188
        const ull* vv2   = (const ull*)vv;

        // warp-tile: 15 warps, each 4 t x 3 c
        const int tg = warp / 3, cg = warp % 3;   // valid for warp < 15
        const int t0 = tg * 4,  c0 = cg * 3;
        ull psum[12];
#pragma unroll
        for (int p = 0; p < 12; p++) psum[p] = 0ull;

        for (int T = 0; T < 4; T++) {
            __syncthreads();
            for (int j = tid; j < 375; j += NTHR) {
                int m = T * 375 + j;
                float xm1 = (m > 0) ? sigS[m - 1] : 0.f;
                float x0  = sigS[m];
                float xp1 = sigS[m + 1];
                float a0 = fmaf(Pm[0],  xm1, fmaf(Pm[1],  x0, fmaf(Pm[2],  xp1, Pm[3])));
                float a1 = fmaf(Pm[4],  xm1, fmaf(Pm[5],  x0, fmaf(Pm[6],  xp1, Pm[7])));
                float a2 = fmaf(Pm[8],  xm1, fmaf(Pm[9],  x0, fmaf(Pm[10], xp1, Pm[11])));
                float a3 = fmaf(Pm[12], xm1, fmaf(Pm[13], x0, fmaf(Pm[14], xp1, Pm[15])));

                float p1 = fmaf(a3, fmaf(0.5f, a3, 1.f), 1.f);
                float p0 = fmaf(a3 * a3 * a3, C6, p1);
                float p2 = fmaf(0.5f, a3, 0.5f);
                float q2 = a3 + 1.f;

                float a00 = a0*a0, a01 = a0*a1, a02 = a0*a2;
                float a11 = a1*a1, a12 = a1*a2, a22 = a2*a2;

                coef[ 0*376 + j] = p0;
                coef[ 1*376 + j] = p1 * a0;
                coef[ 2*376 + j] = p1 * a1;
                coef[ 3*376 + j] = p1 * a2;
                coef[ 4*376 + j] = p2 * a00;
                coef[ 5*376 + j] = q2 * a01;
                coef[ 6*376 + j] = q2 * a02;
                coef[ 7*376 + j] = p2 * a11;
                coef[ 8*376 + j] = q2 * a12;
                coef[ 9*376 + j] = p2 * a22;
                coef[10*376 + j] = C6  * a00 * a0;
                coef[11*376 + j] = 0.5f * a00 * a1;
                coef[12*376 + j] = 0.5f * a00 * a2;
                coef[13*376 + j] = 0.5f * a0  * a11;
                coef[14*376 + j] =        a01 * a2;
                coef[15*376 + j] = 0.5f * a0  * a22;
                coef[16*376 + j] = C6  * a11 * a1;
                coef[17*376 + j] = 0.5f * a11 * a2;
                coef[18*376 + j] = 0.5f * a1  * a22;
                coef[19*376 + j] = C6  * a22 * a2;
#pragma unroll
                for (int c = 0; c < 8; c++) {
                    vv[c*376 + j] = fmaf(cw[48 + c*3], xm1,
                                     fmaf(cw[49 + c*3], x0,
                                     fmaf(cw[50 + c*3], xp1, cw[88 + c])));
                }
                vv[8*376 + j] = 1.f;
            }
            __syncthreads();

            if (warp < 15) {
                for (int j = lane; j < 188; j += 32) {
                    ull ca[4], vb[3];
#pragma unroll
                    for (int ti = 0; ti < 4; ti++) ca[ti] = coef2[(t0 + ti) * 188 + j];
#pragma unroll
                    for (int ci = 0; ci < 3; ci++) vb[ci] = vv2[(c0 + ci) * 188 + j];
#pragma unroll
                    for (int ti = 0; ti < 4; ti++)
#pragma unroll
                        for (int ci = 0; ci < 3; ci++)
                            psum[ti*3 + ci] = ffma2(ca[ti], vb[ci], psum[ti*3 + ci]);
                }
            }
        }
        if (warp < 15) {
#pragma unroll
            for (int p = 0; p < 12; p++) {
                float2 f = unpack2(psum[p]);
                float s = f.x + f.y;
#pragma unroll
                for (int off = 16; off; off >>= 1) s += __shfl_xor_sync(0xffffffffu, s, off);
                if (lane == 0) Es[(t0 + p/3) * 9 + (c0 + p%3)] = s;
            }
        }
        __syncthreads();
    }

    // ---- Phase 2: evaluate ctx window [cbase, cbase+776) ----
    for (int j = tid; j < 776; j += NTHR) {
        int l = cbase + j;
        float y0 = (l > 0) ? sigS[l - 1] : 0.f;
        float y1 = sigS[l];
        float y2 = sigS[l + 1];
        float u[20];
        u[0] = 1.f;  u[1] = y0;  u[2] = y1;  u[3] = y2;
        u[4] = y0*y0; u[5] = y0*y1; u[6] = y0*y2; u[7] = y1*y1; u[8] = y1*y2; u[9] = y2*y2;
        u[10] = u[4]*y0; u[11] = u[4]*y1; u[12] = u[4]*y2; u[13] = y0*u[7]; u[14] = u[5]*y2;
        u[15] = y0*u[9]; u[16] = u[7]*y1; u[17] = u[7]*y2; u[18] = y1*u[9]; u[19] = u[9]*y2;

        float cx[8] = {0,0,0,0,0,0,0,0};
        float den = 0.f;
#pragma unroll
        for (int t = 0; t < 20; t++) {
            float ut = u[t];
            den = fmaf(ut, Es[t*9 + 8], den);
#pragma unroll
            for (int c = 0; c < 8; c++) cx[c] = fmaf(ut, Es[t*9 + c], cx[c]);
        }
        float inv = 1.f / den;
#pragma unroll
        for (int c = 0; c < 8; c++) ctx[c * 776 + j] = cx[c] * inv;
    }
    __syncthreads();   // ctx ready (moment scratch dead)

    // ---- Phase 3: conv1 -> h1 window [lbase, lbase+192) ----
    {
        const ull* xsu = (const ull*)ctx;   // row stride 388
        const ull* wsu = (const ull*)w1s;
        const int xoff = 6 * h;             // (4*lbase - cbase)/2 = (736-724)/2
#pragma unroll
        for (int s = 0; s < 3; s++) {
            int q     = warp + 16 * s;      // 0..47
            int cob   = (q & 7) * 4;
            int chunk = q >> 3;             // 0..5
            int ll    = chunk * 32 + lane;  // 0..191
            int lo    = lbase + ll;
            ull acc[4] = {0ull, 0ull, 0ull, 0ull};
            if (lo < 374) {
#pragma unroll
                for (int ci = 0; ci < 8; ci++) {
                    ull x[4];
#pragma unroll
                    for (int kp = 0; kp < 4; kp++) x[kp] = xsu[ci * 388 + xoff + 2 * ll + kp];
#pragma unroll
                    for (int co = 0; co < 4; co++)
#pragma unroll
                        for (int kp = 0; kp < 4; kp++)
                            acc[co] = ffma2(wsu[(cob + co) * 32 + ci * 4 + kp], x[kp], acc[co]);
                }
#pragma unroll
                for (int co = 0; co < 4; co++) {
                    float2 f = unpack2(acc[co]);
                    h1s[(cob + co) * 192 + ll] = f.x + f.y + b1[cob + co];
                }
            } else {
#pragma unroll
                for (int co = 0; co < 4; co++) h1s[(cob + co) * 192 + ll] = 0.f;
            }
        }
    }
    __syncthreads();   // h1 window ready

    // ---- Phase 4: conv2 -> g_h2 global (cols 46h .. 46h+45) ----
    {
        const ull* xsu = (const ull*)h1s;   // row stride 96
        const ull* wsu = (const ull*)w2s;
        int cob = warp * 4;
#pragma unroll
        for (int pass = 0; pass < 2; pass++) {
            int lo_l = pass * 32 + lane;
            if (lo_l < 46) {
                ull acc[4] = {0ull, 0ull, 0ull, 0ull};
#pragma unroll 8
                for (int ci = 0; ci < 32; ci++) {
                    ull x[4];
#pragma unroll
                    for (int kp = 0; kp < 4; kp++) x[kp] = xsu[ci * 96 + 2 * lo_l + kp];
#pragma unroll
                    for (int j = 0; j < 4; j++)
#pragma unroll
                        for (int kp = 0; kp < 4; kp++)
                            acc[j] = ffma2(wsu[(cob + j) * 128 + ci * 4 + kp], x[kp], acc[j]);
                }
                int col = 46 * h + lo_l;
#pragma unroll
                for (int j = 0; j < 4; j++) {
                    float2 f = unpack2(acc[j]);
                    g_h2[(b * 64 + cob + j) * 96 + col] = f.x + f.y + b2[cob + j];
                }
            }
        }
    }
    __threadfence();
    __syncthreads();
    if (tid == 0) svH = atomicAdd(&g_pH[b], 1u) + 1u;
    __syncthreads();

    // ---- Phase 5 (second finisher): conv3 + linear from global g_h2 ----
    if (svH == 2u) {
        __threadfence();   // acquire peer's g_h2 half
        if (warp < 8 && lane < 22) {
            float acc = b3[warp];
            const float* wp = w3 + warp * 512;
#pragma unroll 8
            for (int ci = 0; ci < 64; ci++) {
                const float4* xp = (const float4*)(g_h2 + (b * 64 + ci) * 96 + 4 * lane);
                float4 x0 = xp[0], x1 = xp[1];
                const float* w = wp + ci * 8;
                acc += w[0]*x0.x + w[1]*x0.y + w[2]*x0.z + w[3]*x0.w
                     + w[4]*x1.x + w[5]*x1.y + w[6]*x1.z + w[7]*x1.w;
            }
            flat[warp * 22 + lane] = acc;
        }
        __syncthreads();

        if (warp < 3) {
            float s = 0.f;
            for (int i = lane; i < 176; i += 32) s += wl[warp * 176 + i] * flat[i];
#pragma unroll
            for (int off = 16; off; off >>= 1) s += __shfl_xor_sync(0xffffffffu, s, off);
            if (lane == 0) out[b * 3 + warp] = s + bl[warp];
        }
        __syncthreads();
        if (tid == 0) atomicExch(&g_pH[b], 0u);   // reset for next replay
    }
}

// ---------------- launch ----------------
extern "C" void kernel_launch(void* const* d_in, const int* in_sizes, int n_in,
                              void* d_out, int out_size) {
    const float* signal = (const float*)d_in[0];
    const float* wq = (const float*)d_in[1];
    const float* bq = (const float*)d_in[2];
    const float* wk = (const float*)d_in[3];
    const float* bk = (const float*)d_in[4];
    const float* wv = (const float*)d_in[5];
    const float* bv = (const float*)d_in[6];
    const float* w1 = (const float*)d_in[7];
    const float* b1 = (const float*)d_in[8];
    const float* w2 = (const float*)d_in[9];
    const float* b2 = (const float*)d_in[10];
    const float* w3 = (const float*)d_in[11];
    const float* b3 = (const float*)d_in[12];
    const float* wl = (const float*)d_in[13];
    const float* bl = (const float*)d_in[14];
    float* out = (float*)d_out;

    cudaFuncSetAttribute(fused_kernel, cudaFuncAttributeMaxDynamicSharedMemorySize,
                         SMEM_FLOATS * 4);
    fused_kernel<<<NBLK, NTHR, SMEM_FLOATS * 4>>>(signal, wq, bq, wk, bk, wv, bv,
                                                  w1, b1, w2, b2, w3, b3, wl, bl, out);
}

// round 15
// speedup vs baseline: 1.7334x; 1.3090x over previous
#include <cuda_runtime.h>

#define NBLK 128
#define NTHR 512

// ---------------- scratch (no allocs allowed) ----------------
__device__ float g_EsP[32][4][180];      // moment partials per (batch, quarter)
__device__ float g_h2[32 * 64 * 96];     // [b][co][col], col padded 92->96
__device__ unsigned g_bA[32];            // per-batch moment barrier (monotonic)
__device__ unsigned g_pH[32];            // head ticket per batch (target 4)

// ---------------- f32x2 helpers ----------------
typedef unsigned long long ull;

__device__ __forceinline__ float2 unpack2(ull v) {
    float2 f; asm("mov.b64 {%0, %1}, %2;" : "=f"(f.x), "=f"(f.y) : "l"(v)); return f;
}
__device__ __forceinline__ ull ffma2(ull a, ull b, ull c) {
    ull d; asm("fma.rn.f32x2 %0, %1, %2, %3;" : "=l"(d) : "l"(a), "l"(b), "l"(c)); return d;
}

// dynamic smem layout (floats)
#define OFF_SIG   0         // 1504
#define OFF_SCR   1504      // moments: coef 20x376 @1504, vv 9x376 @9024 (ends 12408)
#define OFF_CTX   1504      // [8][392] = 3136 (aliases scratch, used after barrier)
#define OFF_H1    4640      // [32][96] = 3072
#define OFF_W1    12408     // 2048
#define OFF_W2    14456     // 16384
#define SMEM_FLOATS 30840   // 123360 bytes

// ================= block = (batch, quarter); one barrier + one ticket per batch ==
__global__ void __launch_bounds__(NTHR, 1) fused_kernel(
        const float* __restrict__ sig,
        const float* __restrict__ wq, const float* __restrict__ bq,
        const float* __restrict__ wk, const float* __restrict__ bk,
        const float* __restrict__ wv, const float* __restrict__ bv,
        const float* __restrict__ w1, const float* __restrict__ b1,
        const float* __restrict__ w2, const float* __restrict__ b2,
        const float* __restrict__ w3, const float* __restrict__ b3,
        const float* __restrict__ wl, const float* __restrict__ bl,
        float* __restrict__ out) {
    extern __shared__ float smbuf[];
    __shared__ float cw[96];
    __shared__ float Pm[16];
    __shared__ float Es[184];
    __shared__ float flat[176];
    __shared__ unsigned svH;

    const int tid  = threadIdx.x;
    const int warp = tid >> 5;
    const int lane = tid & 31;
    const int b    = blockIdx.x >> 2;
    const int q    = blockIdx.x & 3;

    const float QS = 0.02581988897471611f;  // 1/sqrt(1500)
    const float C6 = 0.16666666666666666f;

    float* sigS = smbuf + OFF_SIG;
    float* ctx  = smbuf + OFF_CTX;   // [8][392], global col = 368q + j
    float* h1s  = smbuf + OFF_H1;    // [32][96],  global lo  = 92q + ll
    float* w1s  = smbuf + OFF_W1;
    float* w2s  = smbuf + OFF_W2;

    // ---- load constants / signal / weights ----
    if (tid < 24)      cw[tid] = wq[tid];
    else if (tid < 48) cw[tid] = wk[tid - 24];
    else if (tid < 72) cw[tid] = wv[tid - 48];
    else if (tid < 80) cw[tid] = bq[tid - 72];
    else if (tid < 88) cw[tid] = bk[tid - 80];
    else if (tid < 96) cw[tid] = bv[tid - 88];
    else if (tid < 112) {
        int p = tid - 96, j = p >> 2, i = p & 3;
        float s = 0.f;
#pragma unroll
        for (int c = 0; c < 8; c++) {
            float qv = (j < 3) ? wq[c*3 + j] : bq[c];
            float kv = (i < 3) ? wk[c*3 + i] : bk[c];
            s = fmaf(qv, kv, s);
        }
        Pm[p] = s * QS;
    }
    {
        const float* sigb = sig + b * 1500;
        for (int i = tid; i < 1500; i += NTHR) sigS[i] = sigb[i];
        if (tid < 4) sigS[1500 + tid] = 0.f;
        for (int i = tid; i < 2048; i += NTHR) w1s[i] = w1[i];
        const float4* w4 = (const float4*)w2;
        float4* ws4 = (float4*)w2s;
        for (int i = tid; i < 4096; i += NTHR) ws4[i] = w4[i];
    }

    // ---- Phase 1: moment partials for m-tile q (375 cols) ----
    {
        float* coef = smbuf + 1504;   // [20][376]
        float* vv   = smbuf + 9024;   // [9][376], row 8 = ones
        if (tid < 20) coef[tid * 376 + 375] = 0.f;
        else if (tid < 29) vv[(tid - 20) * 376 + 375] = 0.f;
        __syncthreads();   // sig/Pm/pads ready

        for (int j = tid; j < 375; j += NTHR) {
            int m = q * 375 + j;
            float xm1 = (m > 0) ? sigS[m - 1] : 0.f;
            float x0  = sigS[m];
            float xp1 = sigS[m + 1];   // sigS[1500]=0 pad covers m=1499
            float a0 = fmaf(Pm[0],  xm1, fmaf(Pm[1],  x0, fmaf(Pm[2],  xp1, Pm[3])));
            float a1 = fmaf(Pm[4],  xm1, fmaf(Pm[5],  x0, fmaf(Pm[6],  xp1, Pm[7])));
            float a2 = fmaf(Pm[8],  xm1, fmaf(Pm[9],  x0, fmaf(Pm[10], xp1, Pm[11])));
            float a3 = fmaf(Pm[12], xm1, fmaf(Pm[13], x0, fmaf(Pm[14], xp1, Pm[15])));

            float p1 = fmaf(a3, fmaf(0.5f, a3, 1.f), 1.f);     // 1 + a3 + a3^2/2
            float p0 = fmaf(a3 * a3 * a3, C6, p1);             // + a3^3/6
            float p2 = fmaf(0.5f, a3, 0.5f);
            float q2 = a3 + 1.f;

            float a00 = a0*a0, a01 = a0*a1, a02 = a0*a2;
            float a11 = a1*a1, a12 = a1*a2, a22 = a2*a2;

            coef[ 0*376 + j] = p0;
            coef[ 1*376 + j] = p1 * a0;
            coef[ 2*376 + j] = p1 * a1;
            coef[ 3*376 + j] = p1 * a2;
            coef[ 4*376 + j] = p2 * a00;
            coef[ 5*376 + j] = q2 * a01;
            coef[ 6*376 + j] = q2 * a02;
            coef[ 7*376 + j] = p2 * a11;
            coef[ 8*376 + j] = q2 * a12;
            coef[ 9*376 + j] = p2 * a22;
            coef[10*376 + j] = C6  * a00 * a0;
            coef[11*376 + j] = 0.5f * a00 * a1;
            coef[12*376 + j] = 0.5f * a00 * a2;
            coef[13*376 + j] = 0.5f * a0  * a11;
            coef[14*376 + j] =        a01 * a2;
            coef[15*376 + j] = 0.5f * a0  * a22;
            coef[16*376 + j] = C6  * a11 * a1;
            coef[17*376 + j] = 0.5f * a11 * a2;
            coef[18*376 + j] = 0.5f * a1  * a22;
            coef[19*376 + j] = C6  * a22 * a2;
#pragma unroll
            for (int c = 0; c < 8; c++) {
                vv[c*376 + j] = fmaf(cw[48 + c*3], xm1,
                                 fmaf(cw[49 + c*3], x0,
                                 fmaf(cw[50 + c*3], xp1, cw[88 + c])));
            }
            vv[8*376 + j] = 1.f;
        }
        __syncthreads();

        // register-tiled packed dots: 15 warps x (4t x 3c)
        if (warp < 15) {
            const ull* coef2 = (const ull*)coef;   // stride 188
            const ull* vv2   = (const ull*)vv;
            const int t0 = (warp / 3) * 4;
            const int c0 = (warp % 3) * 3;
            ull psum[12];
#pragma unroll
            for (int p = 0; p < 12; p++) psum[p] = 0ull;
            for (int j = lane; j < 188; j += 32) {
                ull ca[4], vb[3];
#pragma unroll
                for (int ti = 0; ti < 4; ti++) ca[ti] = coef2[(t0 + ti) * 188 + j];
#pragma unroll
                for (int ci = 0; ci < 3; ci++) vb[ci] = vv2[(c0 + ci) * 188 + j];
#pragma unroll
                for (int ti = 0; ti < 4; ti++)
#pragma unroll
                    for (int ci = 0; ci < 3; ci++)
                        psum[ti*3 + ci] = ffma2(ca[ti], vb[ci], psum[ti*3 + ci]);
            }
#pragma unroll
            for (int p = 0; p < 12; p++) {
                float2 f = unpack2(psum[p]);
                float s = f.x + f.y;
#pragma unroll
                for (int off = 16; off; off >>= 1) s += __shfl_xor_sync(0xffffffffu, s, off);
                if (lane == 0) g_EsP[b][q][(t0 + p/3) * 9 + (c0 + p%3)] = s;
            }
        }
    }

    // ---- per-batch barrier over 4 sibling blocks (monotonic, replay-safe) ----
    __syncthreads();
    if (tid == 0) {
        __threadfence();
        unsigned a = atomicAdd(&g_bA[b], 1u) + 1u;
        unsigned target = ((a - 1u) / 4u + 1u) * 4u;
        while (*(volatile unsigned*)&g_bA[b] < target) { }
        __threadfence();
    }
    __syncthreads();

    // sum partials into Es
    if (tid < 180) {
        float s = 0.f;
#pragma unroll
        for (int Q = 0; Q < 4; Q++) s += g_EsP[b][Q][tid];
        Es[tid] = s;
    }
    __syncthreads();   // Es ready; moment scratch dead -> ctx/h1 reuse safe

    // ---- Phase 2: evaluate ctx window [368q, 368q+388) ----
    for (int j = tid; j < 388; j += NTHR) {
        int l = 368 * q + j;            // max 1491 < 1500 always
        float y0 = (l > 0) ? sigS[l - 1] : 0.f;
        float y1 = sigS[l];
        float y2 = sigS[l + 1];
        float u[20];
        u[0] = 1.f;  u[1] = y0;  u[2] = y1;  u[3] = y2;
        u[4] = y0*y0; u[5] = y0*y1; u[6] = y0*y2; u[7] = y1*y1; u[8] = y1*y2; u[9] = y2*y2;
        u[10] = u[4]*y0; u[11] = u[4]*y1; u[12] = u[4]*y2; u[13] = y0*u[7]; u[14] = u[5]*y2;
        u[15] = y0*u[9]; u[16] = u[7]*y1; u[17] = u[7]*y2; u[18] = y1*u[9]; u[19] = u[9]*y2;

        float cx[8] = {0,0,0,0,0,0,0,0};
        float den = 0.f;
#pragma unroll
        for (int t = 0; t < 20; t++) {
            float ut = u[t];
            den = fmaf(ut, Es[t*9 + 8], den);
#pragma unroll
            for (int c = 0; c < 8; c++) cx[c] = fmaf(ut, Es[t*9 + c], cx[c]);
        }
        float inv = 1.f / den;
#pragma unroll
        for (int c = 0; c < 8; c++) ctx[c * 392 + j] = cx[c] * inv;
    }
    __syncthreads();   // ctx window ready

    // ---- Phase 3: conv1 -> h1 window [92q, 92q+96) (local ll = 0..95) ----
    {
        const ull* xsu = (const ull*)ctx;   // row stride 196; input ull = 2*ll + kp
        const ull* wsu = (const ull*)w1s;
#pragma unroll
        for (int s = 0; s < 3; s++) {
            int task  = warp + 16 * s;      // 0..47
            int co    = (task & 15) * 2;    // co group of 2
            int chunk = task >> 4;          // 0..2
            int ll    = chunk * 32 + lane;  // 0..95 (all valid: max lo = 371 < 374)
            ull acc[2] = {0ull, 0ull};
#pragma unroll
            for (int ci = 0; ci < 8; ci++) {
                ull x[4];
#pragma unroll
                for (int kp = 0; kp < 4; kp++) x[kp] = xsu[ci * 196 + 2 * ll + kp];
#pragma unroll
                for (int c2 = 0; c2 < 2; c2++)
#pragma unroll
                    for (int kp = 0; kp < 4; kp++)
                        acc[c2] = ffma2(wsu[(co + c2) * 32 + ci * 4 + kp], x[kp], acc[c2]);
            }
#pragma unroll
            for (int c2 = 0; c2 < 2; c2++) {
                float2 f = unpack2(acc[c2]);
                h1s[(co + c2) * 96 + ll] = f.x + f.y + b1[co + c2];
            }
        }
    }
    __syncthreads();   // h1 window ready

    // ---- Phase 4: conv2 -> g_h2 cols [23q, 23q+23) ----
    {
        const ull* xsu = (const ull*)h1s;   // row stride 48; input ull = 2*cl + kp
        const ull* wsu = (const ull*)w2s;
        int cob = warp * 4;
        int cl  = lane;
        if (cl < 23) {
            ull acc[4] = {0ull, 0ull, 0ull, 0ull};
#pragma unroll 8
            for (int ci = 0; ci < 32; ci++) {
                ull x[4];
#pragma unroll
                for (int kp = 0; kp < 4; kp++) x[kp] = xsu[ci * 48 + 2 * cl + kp];
#pragma unroll
                for (int j = 0; j < 4; j++)
#pragma unroll
                    for (int kp = 0; kp < 4; kp++)
                        acc[j] = ffma2(wsu[(cob + j) * 128 + ci * 4 + kp], x[kp], acc[j]);
            }
            int col = 23 * q + cl;
#pragma unroll
            for (int j = 0; j < 4; j++) {
                float2 f = unpack2(acc[j]);
                g_h2[(b * 64 + cob + j) * 96 + col] = f.x + f.y + b2[cob + j];
            }
        }
    }
    __threadfence();
    __syncthreads();
    if (tid == 0) svH = atomicAdd(&g_pH[b], 1u) + 1u;
    __syncthreads();

    // ---- Phase 5 (4th finisher): conv3 + linear from global g_h2 ----
    if (svH == 4u) {
        __threadfence();   // acquire peers' g_h2 slices
        if (warp < 8 && lane < 22) {
            float acc = b3[warp];
            const float* wp = w3 + warp * 512;
#pragma unroll 8
            for (int ci = 0; ci < 64; ci++) {
                const float4* xp = (const float4*)(g_h2 + (b * 64 + ci) * 96 + 4 * lane);
                float4 x0 = xp[0], x1 = xp[1];
                const float* w = wp + ci * 8;
                acc += w[0]*x0.x + w[1]*x0.y + w[2]*x0.z + w[3]*x0.w
                     + w[4]*x1.x + w[5]*x1.y + w[6]*x1.z + w[7]*x1.w;
            }
            flat[warp * 22 + lane] = acc;
        }
        __syncthreads();

        if (warp < 3) {
            float s = 0.f;
            for (int i = lane; i < 176; i += 32) s += wl[warp * 176 + i] * flat[i];
#pragma unroll
            for (int off = 16; off; off >>= 1) s += __shfl_xor_sync(0xffffffffu, s, off);
            if (lane == 0) out[b * 3 + warp] = s + bl[warp];
        }
        __syncthreads();
        if (tid == 0) atomicExch(&g_pH[b], 0u);   // reset for next replay
    }
}

// ---------------- launch ----------------
extern "C" void kernel_launch(void* const* d_in, const int* in_sizes, int n_in,
                              void* d_out, int out_size) {
    const float* signal = (const float*)d_in[0];
    const float* wq = (const float*)d_in[1];
    const float* bq = (const float*)d_in[2];
    const float* wk = (const float*)d_in[3];
    const float* bk = (const float*)d_in[4];
    const float* wv = (const float*)d_in[5];
    const float* bv = (const float*)d_in[6];
    const float* w1 = (const float*)d_in[7];
    const float* b1 = (const float*)d_in[8];
    const float* w2 = (const float*)d_in[9];
    const float* b2 = (const float*)d_in[10];
    const float* w3 = (const float*)d_in[11];
    const float* b3 = (const float*)d_in[12];
    const float* wl = (const float*)d_in[13];
    const float* bl = (const float*)d_in[14];
    float* out = (float*)d_out;

    cudaFuncSetAttribute(fused_kernel, cudaFuncAttributeMaxDynamicSharedMemorySize,
                         SMEM_FLOATS * 4);
    fused_kernel<<<NBLK, NTHR, SMEM_FLOATS * 4>>>(signal, wq, bq, wk, bk, wv, bv,
                                                  w1, b1, w2, b2, w3, b3, wl, bl, out);
}

// round 17
// speedup vs baseline: 1.9597x; 1.1306x over previous
#include <cuda_runtime.h>

#define NBLK 128
#define NTHR 512

// ---------------- scratch (no allocs allowed) ----------------
__device__ float g_EsP[32][4][180];      // moment partials per (batch, quarter)
__device__ float g_outP[32][4][3];       // partial logits per (batch, quarter)
__device__ unsigned g_bA[32];            // per-batch moment barrier (monotonic)
__device__ unsigned g_pH[32];            // head ticket per batch (target 4)

// ---------------- f32x2 helpers ----------------
typedef unsigned long long ull;

__device__ __forceinline__ float2 unpack2(ull v) {
    float2 f; asm("mov.b64 {%0, %1}, %2;" : "=f"(f.x), "=f"(f.y) : "l"(v)); return f;
}
__device__ __forceinline__ ull ffma2(ull a, ull b, ull c) {
    ull d; asm("fma.rn.f32x2 %0, %1, %2, %3;" : "=l"(d) : "l"(a), "l"(b), "l"(c)); return d;
}

// dynamic smem layout (floats)
#define OFF_SIG   0         // 1504
// moments scratch (pre-barrier): coef @1504 [20][376], vv @9024 [9][376] -> ends 12408
#define OFF_CTX   1504      // [8][392] = 3136 (post-barrier alias)
#define OFF_H1    4640      // [32][96] = 3072
#define OFF_H2    7712      // [64][24] = 1536
#define OFF_W3    12408     // 4096 (pre-barrier only)
#define OFF_A     16504     // [3][64][24] = 4608
#define OFF_W1    21112     // 2048
#define OFF_W2    23160     // 16384
#define SMEM_FLOATS 39544   // 158176 bytes

// ================= block = (batch, quarter); barrier hidden behind A-matrix build ==
__global__ void __launch_bounds__(NTHR, 1) fused_kernel(
        const float* __restrict__ sig,
        const float* __restrict__ wq, const float* __restrict__ bq,
        const float* __restrict__ wk, const float* __restrict__ bk,
        const float* __restrict__ wv, const float* __restrict__ bv,
        const float* __restrict__ w1, const float* __restrict__ b1,
        const float* __restrict__ w2, const float* __restrict__ b2,
        const float* __restrict__ w3, const float* __restrict__ b3,
        const float* __restrict__ wl, const float* __restrict__ bl,
        float* __restrict__ out) {
    extern __shared__ float smbuf[];
    __shared__ float cw[96];
    __shared__ float Pm[16];
    __shared__ float Es[184];
    __shared__ float wls[528];
    __shared__ float sCb3[3];
    __shared__ float wred[48];
    __shared__ unsigned svH, svA;

    const int tid  = threadIdx.x;
    const int warp = tid >> 5;
    const int lane = tid & 31;
    const int b    = blockIdx.x >> 2;
    const int q    = blockIdx.x & 3;

    const float QS = 0.02581988897471611f;  // 1/sqrt(1500)
    const float C6 = 0.16666666666666666f;

    float* sigS = smbuf + OFF_SIG;
    float* ctx  = smbuf + OFF_CTX;   // [8][392], global col = 368q + j
    float* h1s  = smbuf + OFF_H1;    // [32][96],  global lo  = 92q + ll
    float* h2s  = smbuf + OFF_H2;    // [64][24],  global col = 23q + cl
    float* w3s  = smbuf + OFF_W3;
    float* Aloc = smbuf + OFF_A;     // [3][64][24]
    float* w1s  = smbuf + OFF_W1;
    float* w2s  = smbuf + OFF_W2;

    // ---- load constants / signal / weights ----
    if (tid < 24)      cw[tid] = wq[tid];
    else if (tid < 48) cw[tid] = wk[tid - 24];
    else if (tid < 72) cw[tid] = wv[tid - 48];
    else if (tid < 80) cw[tid] = bq[tid - 72];
    else if (tid < 88) cw[tid] = bk[tid - 80];
    else if (tid < 96) cw[tid] = bv[tid - 88];
    else if (tid < 112) {
        int p = tid - 96, j = p >> 2, i = p & 3;
        float s = 0.f;
#pragma unroll
        for (int c = 0; c < 8; c++) {
            float qv = (j < 3) ? wq[c*3 + j] : bq[c];
            float kv = (i < 3) ? wk[c*3 + i] : bk[c];
            s = fmaf(qv, kv, s);
        }
        Pm[p] = s * QS;
    }
    {
        const float4* s4 = (const float4*)(sig + b * 1500);
        float4* d4 = (float4*)sigS;
        for (int i = tid; i < 375; i += NTHR) d4[i] = s4[i];
        if (tid < 4) sigS[1500 + tid] = 0.f;
        for (int i = tid; i < 2048; i += NTHR) w1s[i] = w1[i];
        const float4* w4 = (const float4*)w2;
        float4* ws4 = (float4*)w2s;
        for (int i = tid; i < 4096; i += NTHR) ws4[i] = w4[i];
        const float4* w34 = (const float4*)w3;
        float4* w3d = (float4*)w3s;
        for (int i = tid; i < 1024; i += NTHR) w3d[i] = w34[i];
        for (int i = tid; i < 528; i += NTHR) wls[i] = wl[i];   // FIX: was `if (tid < 528)` with 512 threads
    }

    // ---- Phase 1: moment partials for m-tile q (375 cols) ----
    {
        float* coef = smbuf + 1504;   // [20][376]
        float* vv   = smbuf + 9024;   // [9][376], row 8 = ones
        if (tid < 20) coef[tid * 376 + 375] = 0.f;
        else if (tid < 49) { int c = tid - 20; if (c < 9) vv[c * 376 + 375] = 0.f; }
        __syncthreads();   // sig/Pm/weights/pads ready

        for (int j = tid; j < 375; j += NTHR) {
            int m = q * 375 + j;
            float xm1 = (m > 0) ? sigS[m - 1] : 0.f;
            float x0  = sigS[m];
            float xp1 = sigS[m + 1];
            float a0 = fmaf(Pm[0],  xm1, fmaf(Pm[1],  x0, fmaf(Pm[2],  xp1, Pm[3])));
            float a1 = fmaf(Pm[4],  xm1, fmaf(Pm[5],  x0, fmaf(Pm[6],  xp1, Pm[7])));
            float a2 = fmaf(Pm[8],  xm1, fmaf(Pm[9],  x0, fmaf(Pm[10], xp1, Pm[11])));
            float a3 = fmaf(Pm[12], xm1, fmaf(Pm[13], x0, fmaf(Pm[14], xp1, Pm[15])));

            float p1 = fmaf(a3, fmaf(0.5f, a3, 1.f), 1.f);     // 1 + a3 + a3^2/2
            float p0 = fmaf(a3 * a3 * a3, C6, p1);             // + a3^3/6
            float p2 = fmaf(0.5f, a3, 0.5f);
            float q2 = a3 + 1.f;

            float a00 = a0*a0, a01 = a0*a1, a02 = a0*a2;
            float a11 = a1*a1, a12 = a1*a2, a22 = a2*a2;

            coef[ 0*376 + j] = p0;
            coef[ 1*376 + j] = p1 * a0;
            coef[ 2*376 + j] = p1 * a1;
            coef[ 3*376 + j] = p1 * a2;
            coef[ 4*376 + j] = p2 * a00;
            coef[ 5*376 + j] = q2 * a01;
            coef[ 6*376 + j] = q2 * a02;
            coef[ 7*376 + j] = p2 * a11;
            coef[ 8*376 + j] = q2 * a12;
            coef[ 9*376 + j] = p2 * a22;
            coef[10*376 + j] = C6  * a00 * a0;
            coef[11*376 + j] = 0.5f * a00 * a1;
            coef[12*376 + j] = 0.5f * a00 * a2;
            coef[13*376 + j] = 0.5f * a0  * a11;
            coef[14*376 + j] =        a01 * a2;
            coef[15*376 + j] = 0.5f * a0  * a22;
            coef[16*376 + j] = C6  * a11 * a1;
            coef[17*376 + j] = 0.5f * a11 * a2;
            coef[18*376 + j] = 0.5f * a1  * a22;
            coef[19*376 + j] = C6  * a22 * a2;
#pragma unroll
            for (int c = 0; c < 8; c++) {
                vv[c*376 + j] = fmaf(cw[48 + c*3], xm1,
                                 fmaf(cw[49 + c*3], x0,
                                 fmaf(cw[50 + c*3], xp1, cw[88 + c])));
            }
            vv[8*376 + j] = 1.f;
        }
        __syncthreads();

        // register-tiled packed dots: 15 warps x (4t x 3c)
        if (warp < 15) {
            const ull* coef2 = (const ull*)coef;   // stride 188
            const ull* vv2   = (const ull*)vv;
            const int t0 = (warp / 3) * 4;
            const int c0 = (warp % 3) * 3;
            ull psum[12];
#pragma unroll
            for (int p = 0; p < 12; p++) psum[p] = 0ull;
            for (int j = lane; j < 188; j += 32) {
                ull ca[4], vb[3];
#pragma unroll
                for (int ti = 0; ti < 4; ti++) ca[ti] = coef2[(t0 + ti) * 188 + j];
#pragma unroll
                for (int ci = 0; ci < 3; ci++) vb[ci] = vv2[(c0 + ci) * 188 + j];
#pragma unroll
                for (int ti = 0; ti < 4; ti++)
#pragma unroll
                    for (int ci = 0; ci < 3; ci++)
                        psum[ti*3 + ci] = ffma2(ca[ti], vb[ci], psum[ti*3 + ci]);
            }
#pragma unroll
            for (int p = 0; p < 12; p++) {
                float2 f = unpack2(psum[p]);
                float s = f.x + f.y;
#pragma unroll
                for (int off = 16; off; off >>= 1) s += __shfl_xor_sync(0xffffffffu, s, off);
                if (lane == 0) g_EsP[b][q][(t0 + p/3) * 9 + (c0 + p%3)] = s;
            }
        }
    }

    // ---- arrive at per-batch barrier EARLY, then build A while waiting ----
    __syncthreads();   // all g_EsP writes done block-wide
    if (tid == 0) {
        __threadfence();
        svA = atomicAdd(&g_bA[b], 1u) + 1u;
    }

    // A[k][ci][cl]: head collapsed to linear form over this block's 23 h2 cols
    for (int o = tid; o < 4416; o += NTHR) {
        int k  = o / 1472;
        int r  = o - k * 1472;
        int ci = r / 23;
        int cl = r - ci * 23;
        int col = 23 * q + cl;
        int lo_s = (col >= 7) ? ((col - 4) >> 2) : 0;
        int lo_e = min(21, col >> 2);
        float a = 0.f;
        for (int lo3 = lo_s; lo3 <= lo_e; lo3++) {
            int kk = col - 4 * lo3;
#pragma unroll
            for (int co3 = 0; co3 < 8; co3++)
                a = fmaf(wls[k*176 + co3*22 + lo3], w3s[(co3*64 + ci)*8 + kk], a);
        }
        Aloc[(k*64 + ci)*24 + cl] = a;
    }
    // Cb3[k] = sum_j wl[k][j] * b3[j/22]  (only q==0 adds it)
    if (warp < 3) {
        float s = 0.f;
        for (int j = lane; j < 176; j += 32) s = fmaf(wls[warp*176 + j], b3[j / 22], s);
#pragma unroll
        for (int off = 16; off; off >>= 1) s += __shfl_xor_sync(0xffffffffu, s, off);
        if (lane == 0) sCb3[warp] = s;
    }

    // complete the barrier
    if (tid == 0) {
        unsigned target = ((svA - 1u) / 4u + 1u) * 4u;
        while (*(volatile unsigned*)&g_bA[b] < target) { }
        __threadfence();
    }
    __syncthreads();

    // sum partials into Es
    if (tid < 180) {
        float s = 0.f;
#pragma unroll
        for (int Q = 0; Q < 4; Q++) s += g_EsP[b][Q][tid];
        Es[tid] = s;
    }
    __syncthreads();   // Es ready; moment scratch dead

    // ---- Phase 2: evaluate ctx window [368q, 368q+388) ----
    for (int j = tid; j < 388; j += NTHR) {
        int l = 368 * q + j;
        float y0 = (l > 0) ? sigS[l - 1] : 0.f;
        float y1 = sigS[l];
        float y2 = sigS[l + 1];
        float u[20];
        u[0] = 1.f;  u[1] = y0;  u[2] = y1;  u[3] = y2;
        u[4] = y0*y0; u[5] = y0*y1; u[6] = y0*y2; u[7] = y1*y1; u[8] = y1*y2; u[9] = y2*y2;
        u[10] = u[4]*y0; u[11] = u[4]*y1; u[12] = u[4]*y2; u[13] = y0*u[7]; u[14] = u[5]*y2;
        u[15] = y0*u[9]; u[16] = u[7]*y1; u[17] = u[7]*y2; u[18] = y1*u[9]; u[19] = u[9]*y2;

        float cx[8] = {0,0,0,0,0,0,0,0};
        float den = 0.f;
#pragma unroll
        for (int t = 0; t < 20; t++) {
            float ut = u[t];
            den = fmaf(ut, Es[t*9 + 8], den);
#pragma unroll
            for (int c = 0; c < 8; c++) cx[c] = fmaf(ut, Es[t*9 + c], cx[c]);
        }
        float inv = 1.f / den;
#pragma unroll
        for (int c = 0; c < 8; c++) ctx[c * 392 + j] = cx[c] * inv;
    }
    __syncthreads();   // ctx window ready

    // ---- Phase 3: conv1 -> h1 window [92q, 92q+96) ----
    {
        const ull* xsu = (const ull*)ctx;   // row stride 196
        const ull* wsu = (const ull*)w1s;
#pragma unroll
        for (int s = 0; s < 3; s++) {
            int task  = warp + 16 * s;      // 0..47
            int co    = (task & 15) * 2;
            int chunk = task >> 4;          // 0..2
            int ll    = chunk * 32 + lane;  // 0..95
            ull acc[2] = {0ull, 0ull};
#pragma unroll
            for (int ci = 0; ci < 8; ci++) {
                ull x[4];
#pragma unroll
                for (int kp = 0; kp < 4; kp++) x[kp] = xsu[ci * 196 + 2 * ll + kp];
#pragma unroll
                for (int c2 = 0; c2 < 2; c2++)
#pragma unroll
                    for (int kp = 0; kp < 4; kp++)
                        acc[c2] = ffma2(wsu[(co + c2) * 32 + ci * 4 + kp], x[kp], acc[c2]);
            }
#pragma unroll
            for (int c2 = 0; c2 < 2; c2++) {
                float2 f = unpack2(acc[c2]);
                h1s[(co + c2) * 96 + ll] = f.x + f.y + b1[co + c2];
            }
        }
    }
    __syncthreads();   // h1 window ready

    // ---- Phase 4: conv2 -> h2s (smem) ----
    {
        const ull* xsu = (const ull*)h1s;   // row stride 48
        const ull* wsu = (const ull*)w2s;
        int cob = warp * 4;
        int cl  = lane;
        if (cl < 23) {
            ull acc[4] = {0ull, 0ull, 0ull, 0ull};
#pragma unroll 8
            for (int ci = 0; ci < 32; ci++) {
                ull x[4];
#pragma unroll
                for (int kp = 0; kp < 4; kp++) x[kp] = xsu[ci * 48 + 2 * cl + kp];
#pragma unroll
                for (int j = 0; j < 4; j++)
#pragma unroll
                    for (int kp = 0; kp < 4; kp++)
                        acc[j] = ffma2(wsu[(cob + j) * 128 + ci * 4 + kp], x[kp], acc[j]);
            }
#pragma unroll
            for (int j = 0; j < 4; j++) {
                float2 f = unpack2(acc[j]);
                h2s[(cob + j) * 24 + cl] = f.x + f.y + b2[cob + j];
            }
        }
    }
    __syncthreads();   // h2s ready

    // ---- Phase 5: local head partial (deterministic block reduction) ----
    {
        float pk0 = 0.f, pk1 = 0.f, pk2 = 0.f;
        for (int pr = tid; pr < 1472; pr += NTHR) {
            int ci = pr / 23;
            int cl = pr - ci * 23;
            float hv = h2s[ci * 24 + cl];
            pk0 = fmaf(Aloc[(0*64 + ci)*24 + cl], hv, pk0);
            pk1 = fmaf(Aloc[(1*64 + ci)*24 + cl], hv, pk1);
            pk2 = fmaf(Aloc[(2*64 + ci)*24 + cl], hv, pk2);
        }
#pragma unroll
        for (int off = 16; off; off >>= 1) {
            pk0 += __shfl_xor_sync(0xffffffffu, pk0, off);
            pk1 += __shfl_xor_sync(0xffffffffu, pk1, off);
            pk2 += __shfl_xor_sync(0xffffffffu, pk2, off);
        }
        if (lane == 0) {
            wred[warp * 3 + 0] = pk0;
            wred[warp * 3 + 1] = pk1;
            wred[warp * 3 + 2] = pk2;
        }
        __syncthreads();
        if (tid < 3) {
            float s = 0.f;
#pragma unroll
            for (int w = 0; w < 16; w++) s += wred[w * 3 + tid];
            if (q == 0) s += bl[tid] + sCb3[tid];
            g_outP[b][q][tid] = s;
        }
    }
    __threadfence();
    __syncthreads();
    if (tid == 0) svH = atomicAdd(&g_pH[b], 1u) + 1u;
    __syncthreads();

    // ---- finisher: sum 4 partials, write out ----
    if (svH == 4u) {
        __threadfence();
        if (tid < 3) {
            out[b * 3 + tid] = (g_outP[b][0][tid] + g_outP[b][1][tid]) +
                               (g_outP[b][2][tid] + g_outP[b][3][tid]);
        }
        __syncthreads();
        if (tid == 0) atomicExch(&g_pH[b], 0u);   // reset for next replay
    }
}

// ---------------- launch ----------------
extern "C" void kernel_launch(void* const* d_in, const int* in_sizes, int n_in,
                              void* d_out, int out_size) {
    const float* signal = (const float*)d_in[0];
    const float* wq = (const float*)d_in[1];
    const float* bq = (const float*)d_in[2];
    const float* wk = (const float*)d_in[3];
    const float* bk = (const float*)d_in[4];
    const float* wv = (const float*)d_in[5];
    const float* bv = (const float*)d_in[6];
    const float* w1 = (const float*)d_in[7];
    const float* b1 = (const float*)d_in[8];
    const float* w2 = (const float*)d_in[9];
    const float* b2 = (const float*)d_in[10];
    const float* w3 = (const float*)d_in[11];
    const float* b3 = (const float*)d_in[12];
    const float* wl = (const float*)d_in[13];
    const float* bl = (const float*)d_in[14];
    float* out = (float*)d_out;

    cudaFuncSetAttribute(fused_kernel, cudaFuncAttributeMaxDynamicSharedMemorySize,
                         SMEM_FLOATS * 4);
    fused_kernel<<<NBLK, NTHR, SMEM_FLOATS * 4>>>(signal, wq, bq, wk, bk, wv, bv,
                                                  w1, b1, w2, b2, w3, b3, wl, bl, out);
}